// round 12
// baseline (speedup 1.0000x reference)
#include <cuda_runtime.h>
#include <cuda_fp16.h>
#include <cstdint>
#include <math.h>

#define T_TOK 4096
#define H_DIM 768
#define FF_DIM 1536
#define E_NUM 8

// ---------------- device scratch (allocation-free) ----------------
__device__ int   g_cnt[E_NUM];
__device__ int   g_tok[E_NUM * T_TOK];
__device__ float g_gslot[E_NUM * T_TOK];          // gate value per (expert, slot)
__device__ __half g_xh[(size_t)T_TOK * H_DIM];
__device__ __half g_wfch[(size_t)E_NUM * FF_DIM * H_DIM];
__device__ __half g_wprojh[(size_t)E_NUM * H_DIM * FF_DIM];
__device__ __half g_hmidh[(size_t)E_NUM * T_TOK * FF_DIM];

__device__ __forceinline__ uint32_t smem_to_u32(const void* p) {
    uint32_t a;
    asm("{ .reg .u64 t; cvta.to.shared.u64 t, %1; cvt.u32.u64 %0, t; }" : "=r"(a) : "l"(p));
    return a;
}
__device__ __forceinline__ void ldsm_x4(uint32_t& r0, uint32_t& r1, uint32_t& r2, uint32_t& r3,
                                        uint32_t addr) {
    asm volatile("ldmatrix.sync.aligned.m8n8.x4.shared.b16 {%0,%1,%2,%3}, [%4];"
                 : "=r"(r0), "=r"(r1), "=r"(r2), "=r"(r3) : "r"(addr));
}
__device__ __forceinline__ void mma16816(float* d, const uint32_t* a, uint32_t b0, uint32_t b1) {
    asm volatile("mma.sync.aligned.m16n8k16.row.col.f32.f16.f16.f32 "
                 "{%0,%1,%2,%3}, {%4,%5,%6,%7}, {%8,%9}, {%0,%1,%2,%3};"
                 : "+f"(d[0]), "+f"(d[1]), "+f"(d[2]), "+f"(d[3])
                 : "r"(a[0]), "r"(a[1]), "r"(a[2]), "r"(a[3]), "r"(b0), "r"(b1));
}
#define CP_ASYNC16(smem_u32, gptr) \
    asm volatile("cp.async.cg.shared.global [%0], [%1], 16;" :: "r"(smem_u32), "l"(gptr))
#define CP_COMMIT() asm volatile("cp.async.commit_group;")
#define CP_WAIT1()  asm volatile("cp.async.wait_group 1;")

__device__ __forceinline__ float gelu_erf(float v) {
    return 0.5f * v * (1.0f + erff(v * 0.70710678118654752440f));
}

// ---------------- init / zero ----------------
__global__ void init_kernel() {
    if (threadIdx.x < E_NUM) g_cnt[threadIdx.x] = 0;
}
__global__ __launch_bounds__(256) void zero_out_kernel(float4* __restrict__ out) {
    out[blockIdx.x * 256 + threadIdx.x] = make_float4(0.f, 0.f, 0.f, 0.f);
}

// ---------------- gating + fused x->fp16 conversion (single-wave version) ----------------
// 128 blocks x 1024 threads = 32 warps = 32 tokens per block; one wave on 148 SMs
__global__ __launch_bounds__(1024) void gate_kernel(
    const float4* __restrict__ x4, const float4* __restrict__ gw4,
    float* __restrict__ logits_out)
{
    __shared__ float4 s_gw[E_NUM * 192];     // 24 KB
    int tid = threadIdx.x;
    for (int i = tid; i < E_NUM * 192; i += 1024) s_gw[i] = gw4[i];
    __syncthreads();

    int warp = tid >> 5, lane = tid & 31;
    int t = blockIdx.x * 32 + warp;
    uint2* xh2 = (uint2*)g_xh;

    // prefetch all of this token's x row (6 float4 per lane, MLP=6)
    float4 xv[6];
#pragma unroll
    for (int i = 0; i < 6; i++)
        xv[i] = x4[(size_t)t * 192 + lane + 32 * i];

    // emit fp16 copy
#pragma unroll
    for (int i = 0; i < 6; i++) {
        __half2 p0 = __floats2half2_rn(xv[i].x, xv[i].y);
        __half2 p1 = __floats2half2_rn(xv[i].z, xv[i].w);
        uint2 u; u.x = *(uint32_t*)&p0; u.y = *(uint32_t*)&p1;
        xh2[(size_t)t * 192 + lane + 32 * i] = u;
    }

    float acc[E_NUM];
#pragma unroll
    for (int e = 0; e < E_NUM; e++) acc[e] = 0.f;

#pragma unroll
    for (int i = 0; i < 6; i++) {
        int k = lane + 32 * i;
#pragma unroll
        for (int e = 0; e < E_NUM; e++) {
            float4 w = s_gw[e * 192 + k];
            acc[e] = fmaf(xv[i].x, w.x, acc[e]);
            acc[e] = fmaf(xv[i].y, w.y, acc[e]);
            acc[e] = fmaf(xv[i].z, w.z, acc[e]);
            acc[e] = fmaf(xv[i].w, w.w, acc[e]);
        }
    }
#pragma unroll
    for (int e = 0; e < E_NUM; e++) {
#pragma unroll
        for (int o = 16; o > 0; o >>= 1)
            acc[e] += __shfl_xor_sync(0xffffffffu, acc[e], o);
    }

    if (lane == 0) {
        int i0 = 0; float v0 = acc[0];
#pragma unroll
        for (int e = 1; e < E_NUM; e++) if (acc[e] > v0) { v0 = acc[e]; i0 = e; }
        int i1 = -1; float v1 = -3.0e38f;
#pragma unroll
        for (int e = 0; e < E_NUM; e++) if (e != i0 && acc[e] > v1) { v1 = acc[e]; i1 = e; }

        float e1 = expf(v1 - v0);
        float inv = 1.0f / (1.0f + e1);

#pragma unroll
        for (int e = 0; e < E_NUM; e++) logits_out[(size_t)t * E_NUM + e] = acc[e];

        int s0 = atomicAdd(&g_cnt[i0], 1);
        g_tok[i0 * T_TOK + s0] = t;
        g_gslot[i0 * T_TOK + s0] = inv;
        int s1 = atomicAdd(&g_cnt[i1], 1);
        g_tok[i1 * T_TOK + s1] = t;
        g_gslot[i1 * T_TOK + s1] = e1 * inv;
    }
}

// ---------------- fp32 -> fp16 conversion (8 elems / thread) ----------------
__global__ __launch_bounds__(256) void cvt_fp16_kernel(
    const float4* __restrict__ src, uint2* __restrict__ dst)
{
    size_t i = (size_t)blockIdx.x * 256 + threadIdx.x;
    float4 v0 = src[i * 2];
    float4 v1 = src[i * 2 + 1];
    __half2 a = __floats2half2_rn(v0.x, v0.y);
    __half2 b = __floats2half2_rn(v0.z, v0.w);
    __half2 c = __floats2half2_rn(v1.x, v1.y);
    __half2 d = __floats2half2_rn(v1.z, v1.w);
    uint2 u0; u0.x = *(uint32_t*)&a; u0.y = *(uint32_t*)&b;
    uint2 u1; u1.x = *(uint32_t*)&c; u1.y = *(uint32_t*)&d;
    dst[i * 2] = u0;
    dst[i * 2 + 1] = u1;
}

// ---------------- GEMM tile machinery (proven 128x128, BK=64, 3-stage) ----------------
#define NSTAGE 3
#define STG_STRIDE 32768
#define SMEM_BYTES (NSTAGE * STG_STRIDE)

#define LOAD_CHUNK(c, stg) do {                                                 \
    uint32_t ab = sb + (stg) * STG_STRIDE;                                      \
    uint32_t bb = ab + 16384;                                                   \
    _Pragma("unroll")                                                           \
    for (int j = 0; j < 4; j++) {                                               \
        int grp = lc4 + j;                                                      \
        uint32_t soff = (uint32_t)(lrow * 128 + ((grp ^ (lrow & 7)) << 4));     \
        CP_ASYNC16(ab + soff, aptr + (size_t)(c) * 64 + grp * 8);               \
        CP_ASYNC16(bb + soff, bptr + (size_t)(c) * 64 + grp * 8);               \
    }                                                                           \
} while (0)

#define COMPUTE_CHUNK(stg) do {                                                 \
    uint32_t ab = sb + (stg) * STG_STRIDE;                                      \
    uint32_t bb = ab + 16384;                                                   \
    _Pragma("unroll")                                                           \
    for (int kk8 = 0; kk8 < 8; kk8 += 2) {                                      \
        uint32_t af[4][4], bf[2][4];                                            \
        _Pragma("unroll")                                                       \
        for (int i = 0; i < 4; i++) {                                           \
            uint32_t ad = ab + (uint32_t)((wm + 16 * i + arow) * 128)           \
                        + (uint32_t)((((kk8 + asub) ^ l7)) << 4);               \
            ldsm_x4(af[i][0], af[i][1], af[i][2], af[i][3], ad);                \
        }                                                                       \
        _Pragma("unroll")                                                       \
        for (int j2 = 0; j2 < 2; j2++) {                                        \
            uint32_t bd = bb + (uint32_t)((wn + 16 * j2 + brow) * 128)          \
                        + (uint32_t)((((kk8 + bsub) ^ l7)) << 4);               \
            ldsm_x4(bf[j2][0], bf[j2][1], bf[j2][2], bf[j2][3], bd);            \
        }                                                                       \
        _Pragma("unroll")                                                       \
        for (int i = 0; i < 4; i++)                                             \
            _Pragma("unroll")                                                   \
            for (int j = 0; j < 4; j++)                                         \
                mma16816(acc[i][j], af[i], bf[j >> 1][(j & 1) * 2],             \
                         bf[j >> 1][(j & 1) * 2 + 1]);                          \
    }                                                                           \
} while (0)

#define MAINLOOP(NC) do {                                                       \
    LOAD_CHUNK(0, 0); CP_COMMIT();                                              \
    LOAD_CHUNK(1, 1); CP_COMMIT();                                              \
    int cstg = 0, lstg = 2;                                                     \
    for (int c = 0; c < (NC); c++) {                                            \
        CP_WAIT1();                                                             \
        __syncthreads();                                                        \
        if (c + 2 < (NC)) LOAD_CHUNK(c + 2, lstg);                              \
        CP_COMMIT();                                                            \
        COMPUTE_CHUNK(cstg);                                                    \
        lstg = cstg;                                                            \
        cstg = (cstg + 1 == NSTAGE) ? 0 : cstg + 1;                             \
    }                                                                           \
} while (0)

// ---------------- GEMM1 (expert range): hmid = gelu(x_gather @ wfc^T) -> fp16 ----------------
__global__ __launch_bounds__(256, 2) void moe_gemm1_kernel(int ebase)
{
    int e = ebase + blockIdx.z;
    int cnt = g_cnt[e];
    int m0 = blockIdx.y * 128;
    if (m0 >= cnt) return;
    int n0 = blockIdx.x * 128;

    extern __shared__ char smem[];
    uint32_t sb = smem_to_u32(smem);
    int tid = threadIdx.x, wid = tid >> 5, lane = tid & 31;
    int sub = lane >> 3, l7 = lane & 7;
    int wm = (wid >> 2) * 64, wn = (wid & 3) * 32;
    int arow = l7 + ((sub & 1) << 3), asub = sub >> 1;
    int brow = l7 + ((sub >> 1) << 3), bsub = sub & 1;

    int lrow = tid >> 1;
    int lc4 = (tid & 1) * 4;

    int am = m0 + lrow; if (am >= cnt) am = cnt - 1;
    int atok = g_tok[e * T_TOK + am];
    const __half* aptr = g_xh + (size_t)atok * H_DIM;
    const __half* bptr = g_wfch + ((size_t)e * FF_DIM + n0 + lrow) * H_DIM;

    float acc[4][4][4];
#pragma unroll
    for (int i = 0; i < 4; i++)
#pragma unroll
        for (int j = 0; j < 4; j++)
#pragma unroll
            for (int q = 0; q < 4; q++) acc[i][j][q] = 0.f;

    MAINLOOP(H_DIM / 64);

    int ml = lane >> 2;
    int cl = (lane & 3) * 2;
#pragma unroll
    for (int i = 0; i < 4; i++) {
        int r0 = m0 + wm + 16 * i + ml;
        int r1 = r0 + 8;
#pragma unroll
        for (int j = 0; j < 4; j++) {
            int col = n0 + wn + 8 * j + cl;
            if (r0 < cnt) {
                __half2 h = __floats2half2_rn(gelu_erf(acc[i][j][0]), gelu_erf(acc[i][j][1]));
                *(__half2*)&g_hmidh[((size_t)e * T_TOK + r0) * FF_DIM + col] = h;
            }
            if (r1 < cnt) {
                __half2 h = __floats2half2_rn(gelu_erf(acc[i][j][2]), gelu_erf(acc[i][j][3]));
                *(__half2*)&g_hmidh[((size_t)e * T_TOK + r1) * FF_DIM + col] = h;
            }
        }
    }
}

// ---------------- GEMM2 (expert range): out += gate * (hmid @ wproj^T) ----------------
__global__ __launch_bounds__(256, 2) void moe_gemm2_kernel(float* __restrict__ out, int ebase)
{
    int e = ebase + blockIdx.z;
    int cnt = g_cnt[e];
    int m0 = blockIdx.y * 128;
    if (m0 >= cnt) return;
    int n0 = blockIdx.x * 128;

    extern __shared__ char smem[];
    uint32_t sb = smem_to_u32(smem);
    int tid = threadIdx.x, wid = tid >> 5, lane = tid & 31;
    int sub = lane >> 3, l7 = lane & 7;
    int wm = (wid >> 2) * 64, wn = (wid & 3) * 32;
    int arow = l7 + ((sub & 1) << 3), asub = sub >> 1;
    int brow = l7 + ((sub >> 1) << 3), bsub = sub & 1;

    int lrow = tid >> 1;
    int lc4 = (tid & 1) * 4;

    int am = m0 + lrow; if (am >= cnt) am = cnt - 1;
    const __half* aptr = g_hmidh + ((size_t)e * T_TOK + am) * FF_DIM;
    const __half* bptr = g_wprojh + ((size_t)e * H_DIM + n0 + lrow) * FF_DIM;

    float acc[4][4][4];
#pragma unroll
    for (int i = 0; i < 4; i++)
#pragma unroll
        for (int j = 0; j < 4; j++)
#pragma unroll
            for (int q = 0; q < 4; q++) acc[i][j][q] = 0.f;

    MAINLOOP(FF_DIM / 64);

    int ml = lane >> 2;
    int cl = (lane & 3) * 2;
#pragma unroll
    for (int i = 0; i < 4; i++) {
        int r0 = m0 + wm + 16 * i + ml;
        int r1 = r0 + 8;
        int t0 = -1, t1 = -1;
        float gg0 = 0.f, gg1 = 0.f;
        if (r0 < cnt) { t0 = g_tok[e * T_TOK + r0]; gg0 = g_gslot[e * T_TOK + r0]; }
        if (r1 < cnt) { t1 = g_tok[e * T_TOK + r1]; gg1 = g_gslot[e * T_TOK + r1]; }
#pragma unroll
        for (int j = 0; j < 4; j++) {
            int col = n0 + wn + 8 * j + cl;
            if (t0 >= 0) {
                atomicAdd(&out[(size_t)t0 * H_DIM + col],     gg0 * acc[i][j][0]);
                atomicAdd(&out[(size_t)t0 * H_DIM + col + 1], gg0 * acc[i][j][1]);
            }
            if (t1 >= 0) {
                atomicAdd(&out[(size_t)t1 * H_DIM + col],     gg1 * acc[i][j][2]);
                atomicAdd(&out[(size_t)t1 * H_DIM + col + 1], gg1 * acc[i][j][3]);
            }
        }
    }
}

// ---------------- launch ----------------
extern "C" void kernel_launch(void* const* d_in, const int* in_sizes, int n_in,
                              void* d_out, int out_size)
{
    const float* x     = (const float*)d_in[0];
    const float* gw    = (const float*)d_in[1];
    const float* wfc   = (const float*)d_in[2];
    const float* wproj = (const float*)d_in[3];
    float* out    = (float*)d_out;
    float* logits = (float*)d_out + (size_t)T_TOK * H_DIM;

    static cudaStream_t s1 = nullptr, s2 = nullptr;
    static cudaEvent_t ev_fork = nullptr, ev_gate = nullptr, ev_z = nullptr,
                       ev_wp_lo = nullptr, ev_wp_hi = nullptr,
                       ev_d1 = nullptr, ev_d2 = nullptr;
    if (s1 == nullptr) {
        cudaStreamCreateWithFlags(&s1, cudaStreamNonBlocking);
        cudaStreamCreateWithFlags(&s2, cudaStreamNonBlocking);
        cudaEventCreateWithFlags(&ev_fork, cudaEventDisableTiming);
        cudaEventCreateWithFlags(&ev_gate, cudaEventDisableTiming);
        cudaEventCreateWithFlags(&ev_z, cudaEventDisableTiming);
        cudaEventCreateWithFlags(&ev_wp_lo, cudaEventDisableTiming);
        cudaEventCreateWithFlags(&ev_wp_hi, cudaEventDisableTiming);
        cudaEventCreateWithFlags(&ev_d1, cudaEventDisableTiming);
        cudaEventCreateWithFlags(&ev_d2, cudaEventDisableTiming);
        cudaFuncSetAttribute(moe_gemm1_kernel, cudaFuncAttributeMaxDynamicSharedMemorySize, SMEM_BYTES);
        cudaFuncSetAttribute(moe_gemm2_kernel, cudaFuncAttributeMaxDynamicSharedMemorySize, SMEM_BYTES);
    }

    __half* wfch;   cudaGetSymbolAddress((void**)&wfch, g_wfch);
    __half* wprojh; cudaGetSymbolAddress((void**)&wprojh, g_wprojh);

    const size_t WHALF = (size_t)(E_NUM / 2) * FF_DIM * H_DIM;   // elems per weight half
    const int    CVT_BLKS = (int)((WHALF / 8) / 256);

    // main: init, fork point
    init_kernel<<<1, 32>>>();
    cudaEventRecord(ev_fork, 0);

    // s1: wfc experts 0-3
    cudaStreamWaitEvent(s1, ev_fork, 0);
    cvt_fp16_kernel<<<CVT_BLKS, 256, 0, s1>>>((const float4*)wfc, (uint2*)wfch);

    // s2: wfc experts 4-7
    cudaStreamWaitEvent(s2, ev_fork, 0);
    cvt_fp16_kernel<<<CVT_BLKS, 256, 0, s2>>>(
        (const float4*)(wfc + WHALF), (uint2*)(wfch + WHALF));

    // main: gating (also emits fp16 x), then zero + wproj halves (overlap GEMM1 phase)
    gate_kernel<<<T_TOK / 32, 1024>>>((const float4*)x, (const float4*)gw, logits);
    cudaEventRecord(ev_gate, 0);
    zero_out_kernel<<<(T_TOK * H_DIM / 4) / 256, 256>>>((float4*)out);
    cudaEventRecord(ev_z, 0);
    cvt_fp16_kernel<<<CVT_BLKS, 256>>>((const float4*)wproj, (uint2*)wprojh);
    cudaEventRecord(ev_wp_lo, 0);
    cvt_fp16_kernel<<<CVT_BLKS, 256>>>(
        (const float4*)(wproj + WHALF), (uint2*)(wprojh + WHALF));
    cudaEventRecord(ev_wp_hi, 0);

    // two half-pipelines
    dim3 g1(FF_DIM / 128, T_TOK / 128, E_NUM / 2);
    dim3 g2(H_DIM / 128, T_TOK / 128, E_NUM / 2);

    // s1: experts 0-3
    cudaStreamWaitEvent(s1, ev_gate, 0);
    moe_gemm1_kernel<<<g1, 256, SMEM_BYTES, s1>>>(0);
    cudaStreamWaitEvent(s1, ev_z, 0);
    cudaStreamWaitEvent(s1, ev_wp_lo, 0);
    moe_gemm2_kernel<<<g2, 256, SMEM_BYTES, s1>>>(out, 0);
    cudaEventRecord(ev_d1, s1);

    // s2: experts 4-7
    cudaStreamWaitEvent(s2, ev_gate, 0);
    moe_gemm1_kernel<<<g1, 256, SMEM_BYTES, s2>>>(E_NUM / 2);
    cudaStreamWaitEvent(s2, ev_z, 0);
    cudaStreamWaitEvent(s2, ev_wp_hi, 0);
    moe_gemm2_kernel<<<g2, 256, SMEM_BYTES, s2>>>(out, E_NUM / 2);
    cudaEventRecord(ev_d2, s2);

    cudaStreamWaitEvent(0, ev_d1, 0);
    cudaStreamWaitEvent(0, ev_d2, 0);
}

// round 13
// speedup vs baseline: 1.5134x; 1.5134x over previous
#include <cuda_runtime.h>
#include <cuda_fp16.h>
#include <cstdint>
#include <math.h>

#define T_TOK 4096
#define H_DIM 768
#define FF_DIM 1536
#define E_NUM 8

// ---------------- device scratch (allocation-free) ----------------
__device__ int   g_cnt[E_NUM];
__device__ int   g_tok[E_NUM * T_TOK];
__device__ float g_gslot[E_NUM * T_TOK];          // gate value per (expert, slot)
__device__ __half g_xh[(size_t)T_TOK * H_DIM];
__device__ __half g_wfch[(size_t)E_NUM * FF_DIM * H_DIM];
__device__ __half g_wprojh[(size_t)E_NUM * H_DIM * FF_DIM];
__device__ __half g_hmidh[(size_t)E_NUM * T_TOK * FF_DIM];

__device__ __forceinline__ uint32_t smem_to_u32(const void* p) {
    uint32_t a;
    asm("{ .reg .u64 t; cvta.to.shared.u64 t, %1; cvt.u32.u64 %0, t; }" : "=r"(a) : "l"(p));
    return a;
}
__device__ __forceinline__ void ldsm_x4(uint32_t& r0, uint32_t& r1, uint32_t& r2, uint32_t& r3,
                                        uint32_t addr) {
    asm volatile("ldmatrix.sync.aligned.m8n8.x4.shared.b16 {%0,%1,%2,%3}, [%4];"
                 : "=r"(r0), "=r"(r1), "=r"(r2), "=r"(r3) : "r"(addr));
}
__device__ __forceinline__ void mma16816(float* d, const uint32_t* a, uint32_t b0, uint32_t b1) {
    asm volatile("mma.sync.aligned.m16n8k16.row.col.f32.f16.f16.f32 "
                 "{%0,%1,%2,%3}, {%4,%5,%6,%7}, {%8,%9}, {%0,%1,%2,%3};"
                 : "+f"(d[0]), "+f"(d[1]), "+f"(d[2]), "+f"(d[3])
                 : "r"(a[0]), "r"(a[1]), "r"(a[2]), "r"(a[3]), "r"(b0), "r"(b1));
}
#define CP_ASYNC16(smem_u32, gptr) \
    asm volatile("cp.async.cg.shared.global [%0], [%1], 16;" :: "r"(smem_u32), "l"(gptr))
#define CP_COMMIT() asm volatile("cp.async.commit_group;")
#define CP_WAIT1()  asm volatile("cp.async.wait_group 1;")

__device__ __forceinline__ float gelu_erf(float v) {
    return 0.5f * v * (1.0f + erff(v * 0.70710678118654752440f));
}

// ---------------- init / zero ----------------
__global__ void init_kernel() {
    if (threadIdx.x < E_NUM) g_cnt[threadIdx.x] = 0;
}
__global__ __launch_bounds__(256) void zero_out_kernel(float4* __restrict__ out) {
    out[blockIdx.x * 256 + threadIdx.x] = make_float4(0.f, 0.f, 0.f, 0.f);
}

// ---------------- gating + fused x->fp16 conversion ----------------
// 512 threads = 16 warps = 16 tokens per block (R11 config) with two-level
// atomic aggregation: smem counters per block, ONE global atomicAdd per
// (block, expert) instead of one per (token, k).
__global__ __launch_bounds__(512) void gate_kernel(
    const float4* __restrict__ x4, const float4* __restrict__ gw4,
    float* __restrict__ logits_out)
{
    __shared__ float4 s_gw[E_NUM * 192];     // 24 KB
    __shared__ int s_cnt[E_NUM];
    __shared__ int s_base[E_NUM];
    int tid = threadIdx.x;
    if (tid < E_NUM) s_cnt[tid] = 0;
    for (int i = tid; i < E_NUM * 192; i += 512) s_gw[i] = gw4[i];
    __syncthreads();

    int warp = tid >> 5, lane = tid & 31;
    int t = blockIdx.x * 16 + warp;
    uint2* xh2 = (uint2*)g_xh;

    // prefetch all of this token's x row (6 float4 per lane, MLP=6)
    float4 xv[6];
#pragma unroll
    for (int i = 0; i < 6; i++)
        xv[i] = x4[(size_t)t * 192 + lane + 32 * i];

    // emit fp16 copy
#pragma unroll
    for (int i = 0; i < 6; i++) {
        __half2 p0 = __floats2half2_rn(xv[i].x, xv[i].y);
        __half2 p1 = __floats2half2_rn(xv[i].z, xv[i].w);
        uint2 u; u.x = *(uint32_t*)&p0; u.y = *(uint32_t*)&p1;
        xh2[(size_t)t * 192 + lane + 32 * i] = u;
    }

    float acc[E_NUM];
#pragma unroll
    for (int e = 0; e < E_NUM; e++) acc[e] = 0.f;

#pragma unroll
    for (int i = 0; i < 6; i++) {
        int k = lane + 32 * i;
#pragma unroll
        for (int e = 0; e < E_NUM; e++) {
            float4 w = s_gw[e * 192 + k];
            acc[e] = fmaf(xv[i].x, w.x, acc[e]);
            acc[e] = fmaf(xv[i].y, w.y, acc[e]);
            acc[e] = fmaf(xv[i].z, w.z, acc[e]);
            acc[e] = fmaf(xv[i].w, w.w, acc[e]);
        }
    }
#pragma unroll
    for (int e = 0; e < E_NUM; e++) {
#pragma unroll
        for (int o = 16; o > 0; o >>= 1)
            acc[e] += __shfl_xor_sync(0xffffffffu, acc[e], o);
    }

    // per-warp top-2 + local slot reservation (smem atomics)
    int i0 = 0, i1 = -1, l0 = 0, l1 = 0;
    float gate0 = 0.f, gate1 = 0.f;
    if (lane == 0) {
        float v0 = acc[0];
#pragma unroll
        for (int e = 1; e < E_NUM; e++) if (acc[e] > v0) { v0 = acc[e]; i0 = e; }
        float v1 = -3.0e38f;
#pragma unroll
        for (int e = 0; e < E_NUM; e++) if (e != i0 && acc[e] > v1) { v1 = acc[e]; i1 = e; }

        float e1 = expf(v1 - v0);
        float inv = 1.0f / (1.0f + e1);
        gate0 = inv; gate1 = e1 * inv;

#pragma unroll
        for (int e = 0; e < E_NUM; e++) logits_out[(size_t)t * E_NUM + e] = acc[e];

        l0 = atomicAdd(&s_cnt[i0], 1);
        l1 = atomicAdd(&s_cnt[i1], 1);
    }
    __syncthreads();

    // one global atomic per (block, expert)
    if (tid < E_NUM) s_base[tid] = atomicAdd(&g_cnt[tid], s_cnt[tid]);
    __syncthreads();

    if (lane == 0) {
        int s0 = s_base[i0] + l0;
        g_tok[i0 * T_TOK + s0] = t;
        g_gslot[i0 * T_TOK + s0] = gate0;
        int s1 = s_base[i1] + l1;
        g_tok[i1 * T_TOK + s1] = t;
        g_gslot[i1 * T_TOK + s1] = gate1;
    }
}

// ---------------- fp32 -> fp16 conversion (8 elems / thread) ----------------
__global__ __launch_bounds__(256) void cvt_fp16_kernel(
    const float4* __restrict__ src, uint2* __restrict__ dst)
{
    size_t i = (size_t)blockIdx.x * 256 + threadIdx.x;
    float4 v0 = src[i * 2];
    float4 v1 = src[i * 2 + 1];
    __half2 a = __floats2half2_rn(v0.x, v0.y);
    __half2 b = __floats2half2_rn(v0.z, v0.w);
    __half2 c = __floats2half2_rn(v1.x, v1.y);
    __half2 d = __floats2half2_rn(v1.z, v1.w);
    uint2 u0; u0.x = *(uint32_t*)&a; u0.y = *(uint32_t*)&b;
    uint2 u1; u1.x = *(uint32_t*)&c; u1.y = *(uint32_t*)&d;
    dst[i * 2] = u0;
    dst[i * 2 + 1] = u1;
}

// ---------------- GEMM tile machinery (proven 128x128, BK=64, 3-stage) ----------------
#define NSTAGE 3
#define STG_STRIDE 32768
#define SMEM_BYTES (NSTAGE * STG_STRIDE)

#define LOAD_CHUNK(c, stg) do {                                                 \
    uint32_t ab = sb + (stg) * STG_STRIDE;                                      \
    uint32_t bb = ab + 16384;                                                   \
    _Pragma("unroll")                                                           \
    for (int j = 0; j < 4; j++) {                                               \
        int grp = lc4 + j;                                                      \
        uint32_t soff = (uint32_t)(lrow * 128 + ((grp ^ (lrow & 7)) << 4));     \
        CP_ASYNC16(ab + soff, aptr + (size_t)(c) * 64 + grp * 8);               \
        CP_ASYNC16(bb + soff, bptr + (size_t)(c) * 64 + grp * 8);               \
    }                                                                           \
} while (0)

#define COMPUTE_CHUNK(stg) do {                                                 \
    uint32_t ab = sb + (stg) * STG_STRIDE;                                      \
    uint32_t bb = ab + 16384;                                                   \
    _Pragma("unroll")                                                           \
    for (int kk8 = 0; kk8 < 8; kk8 += 2) {                                      \
        uint32_t af[4][4], bf[2][4];                                            \
        _Pragma("unroll")                                                       \
        for (int i = 0; i < 4; i++) {                                           \
            uint32_t ad = ab + (uint32_t)((wm + 16 * i + arow) * 128)           \
                        + (uint32_t)((((kk8 + asub) ^ l7)) << 4);               \
            ldsm_x4(af[i][0], af[i][1], af[i][2], af[i][3], ad);                \
        }                                                                       \
        _Pragma("unroll")                                                       \
        for (int j2 = 0; j2 < 2; j2++) {                                        \
            uint32_t bd = bb + (uint32_t)((wn + 16 * j2 + brow) * 128)          \
                        + (uint32_t)((((kk8 + bsub) ^ l7)) << 4);               \
            ldsm_x4(bf[j2][0], bf[j2][1], bf[j2][2], bf[j2][3], bd);            \
        }                                                                       \
        _Pragma("unroll")                                                       \
        for (int i = 0; i < 4; i++)                                             \
            _Pragma("unroll")                                                   \
            for (int j = 0; j < 4; j++)                                         \
                mma16816(acc[i][j], af[i], bf[j >> 1][(j & 1) * 2],             \
                         bf[j >> 1][(j & 1) * 2 + 1]);                          \
    }                                                                           \
} while (0)

#define MAINLOOP(NC) do {                                                       \
    LOAD_CHUNK(0, 0); CP_COMMIT();                                              \
    LOAD_CHUNK(1, 1); CP_COMMIT();                                              \
    int cstg = 0, lstg = 2;                                                     \
    for (int c = 0; c < (NC); c++) {                                            \
        CP_WAIT1();                                                             \
        __syncthreads();                                                        \
        if (c + 2 < (NC)) LOAD_CHUNK(c + 2, lstg);                              \
        CP_COMMIT();                                                            \
        COMPUTE_CHUNK(cstg);                                                    \
        lstg = cstg;                                                            \
        cstg = (cstg + 1 == NSTAGE) ? 0 : cstg + 1;                             \
    }                                                                           \
} while (0)

// ---------------- GEMM1 (expert range): hmid = gelu(x_gather @ wfc^T) -> fp16 ----------------
__global__ __launch_bounds__(256, 2) void moe_gemm1_kernel(int ebase)
{
    int e = ebase + blockIdx.z;
    int cnt = g_cnt[e];
    int m0 = blockIdx.y * 128;
    if (m0 >= cnt) return;
    int n0 = blockIdx.x * 128;

    extern __shared__ char smem[];
    uint32_t sb = smem_to_u32(smem);
    int tid = threadIdx.x, wid = tid >> 5, lane = tid & 31;
    int sub = lane >> 3, l7 = lane & 7;
    int wm = (wid >> 2) * 64, wn = (wid & 3) * 32;
    int arow = l7 + ((sub & 1) << 3), asub = sub >> 1;
    int brow = l7 + ((sub >> 1) << 3), bsub = sub & 1;

    int lrow = tid >> 1;
    int lc4 = (tid & 1) * 4;

    int am = m0 + lrow; if (am >= cnt) am = cnt - 1;
    int atok = g_tok[e * T_TOK + am];
    const __half* aptr = g_xh + (size_t)atok * H_DIM;
    const __half* bptr = g_wfch + ((size_t)e * FF_DIM + n0 + lrow) * H_DIM;

    float acc[4][4][4];
#pragma unroll
    for (int i = 0; i < 4; i++)
#pragma unroll
        for (int j = 0; j < 4; j++)
#pragma unroll
            for (int q = 0; q < 4; q++) acc[i][j][q] = 0.f;

    MAINLOOP(H_DIM / 64);

    int ml = lane >> 2;
    int cl = (lane & 3) * 2;
#pragma unroll
    for (int i = 0; i < 4; i++) {
        int r0 = m0 + wm + 16 * i + ml;
        int r1 = r0 + 8;
#pragma unroll
        for (int j = 0; j < 4; j++) {
            int col = n0 + wn + 8 * j + cl;
            if (r0 < cnt) {
                __half2 h = __floats2half2_rn(gelu_erf(acc[i][j][0]), gelu_erf(acc[i][j][1]));
                *(__half2*)&g_hmidh[((size_t)e * T_TOK + r0) * FF_DIM + col] = h;
            }
            if (r1 < cnt) {
                __half2 h = __floats2half2_rn(gelu_erf(acc[i][j][2]), gelu_erf(acc[i][j][3]));
                *(__half2*)&g_hmidh[((size_t)e * T_TOK + r1) * FF_DIM + col] = h;
            }
        }
    }
}

// ---------------- GEMM2 (expert range): out += gate * (hmid @ wproj^T) ----------------
__global__ __launch_bounds__(256, 2) void moe_gemm2_kernel(float* __restrict__ out, int ebase)
{
    int e = ebase + blockIdx.z;
    int cnt = g_cnt[e];
    int m0 = blockIdx.y * 128;
    if (m0 >= cnt) return;
    int n0 = blockIdx.x * 128;

    extern __shared__ char smem[];
    uint32_t sb = smem_to_u32(smem);
    int tid = threadIdx.x, wid = tid >> 5, lane = tid & 31;
    int sub = lane >> 3, l7 = lane & 7;
    int wm = (wid >> 2) * 64, wn = (wid & 3) * 32;
    int arow = l7 + ((sub & 1) << 3), asub = sub >> 1;
    int brow = l7 + ((sub >> 1) << 3), bsub = sub & 1;

    int lrow = tid >> 1;
    int lc4 = (tid & 1) * 4;

    int am = m0 + lrow; if (am >= cnt) am = cnt - 1;
    const __half* aptr = g_hmidh + ((size_t)e * T_TOK + am) * FF_DIM;
    const __half* bptr = g_wprojh + ((size_t)e * H_DIM + n0 + lrow) * FF_DIM;

    float acc[4][4][4];
#pragma unroll
    for (int i = 0; i < 4; i++)
#pragma unroll
        for (int j = 0; j < 4; j++)
#pragma unroll
            for (int q = 0; q < 4; q++) acc[i][j][q] = 0.f;

    MAINLOOP(FF_DIM / 64);

    int ml = lane >> 2;
    int cl = (lane & 3) * 2;
#pragma unroll
    for (int i = 0; i < 4; i++) {
        int r0 = m0 + wm + 16 * i + ml;
        int r1 = r0 + 8;
        int t0 = -1, t1 = -1;
        float gg0 = 0.f, gg1 = 0.f;
        if (r0 < cnt) { t0 = g_tok[e * T_TOK + r0]; gg0 = g_gslot[e * T_TOK + r0]; }
        if (r1 < cnt) { t1 = g_tok[e * T_TOK + r1]; gg1 = g_gslot[e * T_TOK + r1]; }
#pragma unroll
        for (int j = 0; j < 4; j++) {
            int col = n0 + wn + 8 * j + cl;
            if (t0 >= 0) {
                atomicAdd(&out[(size_t)t0 * H_DIM + col],     gg0 * acc[i][j][0]);
                atomicAdd(&out[(size_t)t0 * H_DIM + col + 1], gg0 * acc[i][j][1]);
            }
            if (t1 >= 0) {
                atomicAdd(&out[(size_t)t1 * H_DIM + col],     gg1 * acc[i][j][2]);
                atomicAdd(&out[(size_t)t1 * H_DIM + col + 1], gg1 * acc[i][j][3]);
            }
        }
    }
}

// ---------------- launch ----------------
extern "C" void kernel_launch(void* const* d_in, const int* in_sizes, int n_in,
                              void* d_out, int out_size)
{
    const float* x     = (const float*)d_in[0];
    const float* gw    = (const float*)d_in[1];
    const float* wfc   = (const float*)d_in[2];
    const float* wproj = (const float*)d_in[3];
    float* out    = (float*)d_out;
    float* logits = (float*)d_out + (size_t)T_TOK * H_DIM;

    static cudaStream_t s1 = nullptr, s2 = nullptr;
    static cudaEvent_t ev_fork = nullptr, ev_gate = nullptr, ev_z = nullptr,
                       ev_wp_lo = nullptr, ev_wp_hi = nullptr,
                       ev_d1 = nullptr, ev_d2 = nullptr;
    if (s1 == nullptr) {
        cudaStreamCreateWithFlags(&s1, cudaStreamNonBlocking);
        cudaStreamCreateWithFlags(&s2, cudaStreamNonBlocking);
        cudaEventCreateWithFlags(&ev_fork, cudaEventDisableTiming);
        cudaEventCreateWithFlags(&ev_gate, cudaEventDisableTiming);
        cudaEventCreateWithFlags(&ev_z, cudaEventDisableTiming);
        cudaEventCreateWithFlags(&ev_wp_lo, cudaEventDisableTiming);
        cudaEventCreateWithFlags(&ev_wp_hi, cudaEventDisableTiming);
        cudaEventCreateWithFlags(&ev_d1, cudaEventDisableTiming);
        cudaEventCreateWithFlags(&ev_d2, cudaEventDisableTiming);
        cudaFuncSetAttribute(moe_gemm1_kernel, cudaFuncAttributeMaxDynamicSharedMemorySize, SMEM_BYTES);
        cudaFuncSetAttribute(moe_gemm2_kernel, cudaFuncAttributeMaxDynamicSharedMemorySize, SMEM_BYTES);
    }

    __half* wfch;   cudaGetSymbolAddress((void**)&wfch, g_wfch);
    __half* wprojh; cudaGetSymbolAddress((void**)&wprojh, g_wprojh);

    const size_t WHALF = (size_t)(E_NUM / 2) * FF_DIM * H_DIM;   // elems per weight half
    const int    CVT_BLKS = (int)((WHALF / 8) / 256);

    // main: init, fork point
    init_kernel<<<1, 32>>>();
    cudaEventRecord(ev_fork, 0);

    // s1: wfc experts 0-3
    cudaStreamWaitEvent(s1, ev_fork, 0);
    cvt_fp16_kernel<<<CVT_BLKS, 256, 0, s1>>>((const float4*)wfc, (uint2*)wfch);

    // s2: wfc experts 4-7
    cudaStreamWaitEvent(s2, ev_fork, 0);
    cvt_fp16_kernel<<<CVT_BLKS, 256, 0, s2>>>(
        (const float4*)(wfc + WHALF), (uint2*)(wfch + WHALF));

    // main: gating (also emits fp16 x), then zero + wproj halves (overlap GEMM1 phase)
    gate_kernel<<<T_TOK / 16, 512>>>((const float4*)x, (const float4*)gw, logits);
    cudaEventRecord(ev_gate, 0);
    zero_out_kernel<<<(T_TOK * H_DIM / 4) / 256, 256>>>((float4*)out);
    cudaEventRecord(ev_z, 0);
    cvt_fp16_kernel<<<CVT_BLKS, 256>>>((const float4*)wproj, (uint2*)wprojh);
    cudaEventRecord(ev_wp_lo, 0);
    cvt_fp16_kernel<<<CVT_BLKS, 256>>>(
        (const float4*)(wproj + WHALF), (uint2*)(wprojh + WHALF));
    cudaEventRecord(ev_wp_hi, 0);

    // two half-pipelines
    dim3 g1(FF_DIM / 128, T_TOK / 128, E_NUM / 2);
    dim3 g2(H_DIM / 128, T_TOK / 128, E_NUM / 2);

    // s1: experts 0-3
    cudaStreamWaitEvent(s1, ev_gate, 0);
    moe_gemm1_kernel<<<g1, 256, SMEM_BYTES, s1>>>(0);
    cudaStreamWaitEvent(s1, ev_z, 0);
    cudaStreamWaitEvent(s1, ev_wp_lo, 0);
    moe_gemm2_kernel<<<g2, 256, SMEM_BYTES, s1>>>(out, 0);
    cudaEventRecord(ev_d1, s1);

    // s2: experts 4-7
    cudaStreamWaitEvent(s2, ev_gate, 0);
    moe_gemm1_kernel<<<g1, 256, SMEM_BYTES, s2>>>(E_NUM / 2);
    cudaStreamWaitEvent(s2, ev_z, 0);
    cudaStreamWaitEvent(s2, ev_wp_hi, 0);
    moe_gemm2_kernel<<<g2, 256, SMEM_BYTES, s2>>>(out, E_NUM / 2);
    cudaEventRecord(ev_d2, s2);

    cudaStreamWaitEvent(0, ev_d1, 0);
    cudaStreamWaitEvent(0, ev_d2, 0);
}